// round 3
// baseline (speedup 1.0000x reference)
#include <cuda_runtime.h>
#include <cuda_bf16.h>

// S4D forward, exact diagonal-SSM recurrence:
//   a[d,n]  = exp(dt_d * A_n),  A_n = -0.5*(n+1)
//   cb[d,n] = C[d,n]*B[d,n]*expm1(dt_d*A_n)/A_n
//   h_n[l]  = a_n*h_n[l-1] + x[l],   y[l] = sum_n cb_n*h_n[l] + D_d*x[l]
//
// R3: widen warp parallelism at fixed FLOPs. 512 CTAs x 256 thr (4096 warps):
// CTA = 16 channels; 16 threads per channel (2 state-pairs each, FFMA2);
// double-buffered smem partials -> one __syncthreads per 16-step round.

#define BATCH   8
#define LEN     2048
#define DMODEL  1024
#define NSTATE  64

#define WARPS   8
#define CHT     16     // channels per CTA
#define TPC     16     // threads per channel
#define PAIRS   2      // state pairs per thread (4 states)
#define RST     16     // timesteps per reduction round
#define ROWPAD  20     // padded row length (floats): 16B-aligned, bank-spread

typedef unsigned long long u64;

__device__ __forceinline__ u64 pack2(float lo, float hi) {
    u64 r; asm("mov.b64 %0, {%1,%2};" : "=l"(r) : "f"(lo), "f"(hi)); return r;
}
__device__ __forceinline__ void unpack2(u64 v, float& lo, float& hi) {
    asm("mov.b64 {%0,%1}, %2;" : "=f"(lo), "=f"(hi) : "l"(v));
}
__device__ __forceinline__ u64 fma2(u64 a, u64 b, u64 c) {
    u64 d; asm("fma.rn.f32x2 %0, %1, %2, %3;" : "=l"(d) : "l"(a), "l"(b), "l"(c)); return d;
}
__device__ __forceinline__ u64 mul2(u64 a, u64 b) {
    u64 d; asm("mul.rn.f32x2 %0, %1, %2;" : "=l"(d) : "l"(a), "l"(b)); return d;
}

__global__ __launch_bounds__(WARPS * 32)
void s4d_recurrence_kernel(const float* __restrict__ x,
                           const float* __restrict__ log_dt,
                           const float* __restrict__ Bm,
                           const float* __restrict__ Cm,
                           const float* __restrict__ Dv,
                           float* __restrict__ y)
{
    __shared__ float P[2][RST][CHT][ROWPAD];   // 40 KB

    const int lane = threadIdx.x & 31;
    const int w    = threadIdx.x >> 5;
    const int d0   = blockIdx.x * CHT;
    const int b    = blockIdx.y;

    const int c = lane >> 1;            // channel within tile (0..15)
    const int h = lane & 1;             // half
    const int t = w * 2 + h;            // thread index within channel (0..15)
    const int d = d0 + c;

    // ---- per-thread discretized parameters: states 4t .. 4t+3 ----
    u64 a2[PAIRS], cb2[PAIRS], s2[PAIRS];
    {
        const float dt = expf(log_dt[d]);
        #pragma unroll
        for (int i = 0; i < PAIRS; i++) {
            float av[2], cbv[2];
            #pragma unroll
            for (int hh = 0; hh < 2; hh++) {
                const int   n   = 4 * t + 2 * i + hh;
                const float An  = -0.5f * (float)(n + 1);
                const float dtA = dt * An;
                av[hh]  = expf(dtA);
                cbv[hh] = Cm[d * NSTATE + n] * Bm[d * NSTATE + n] * (expm1f(dtA) / An);
            }
            a2[i]  = pack2(av[0], av[1]);
            cb2[i] = pack2(cbv[0], cbv[1]);
            s2[i]  = 0ull;
        }
    }

    const float* xb = x + (size_t)b * LEN * DMODEL + d;   // compute-phase x ptr

    // reduce-phase pointers (lane = channel there)
    const float* xr = x + (size_t)b * LEN * DMODEL + d0 + lane;
    float*       yr = y + (size_t)b * LEN * DMODEL + d0 + lane;
    const float  Dd = (lane < CHT) ? Dv[d0 + lane] : 0.0f;

    #pragma unroll 1
    for (int l0 = 0; l0 < LEN; l0 += 2 * RST) {
        #pragma unroll
        for (int buf = 0; buf < 2; buf++) {
            const int base = l0 + buf * RST;

            // ---- compute: 16 steps, 2-pair FFMA2 recurrence + contraction ----
            #pragma unroll
            for (int r = 0; r < RST; r++) {
                const float xv = xb[(size_t)(base + r) * DMODEL];
                const u64   xx = pack2(xv, xv);
                s2[0] = fma2(a2[0], s2[0], xx);
                s2[1] = fma2(a2[1], s2[1], xx);
                u64 acc = fma2(cb2[1], s2[1], mul2(cb2[0], s2[0]));
                float lo, hi;
                unpack2(acc, lo, hi);
                P[buf][r][c][t] = lo + hi;
            }
            __syncthreads();

            // ---- cross-thread reduce: warp w -> rows r=w, w+8; lane=channel ----
            if (lane < CHT) {
                #pragma unroll
                for (int k = 0; k < 2; k++) {
                    const int r = w + k * WARPS;
                    const float4* row = (const float4*)&P[buf][r][lane][0];
                    const float4 v0 = row[0];
                    const float4 v1 = row[1];
                    const float4 v2 = row[2];
                    const float4 v3 = row[3];
                    const float sum = ((v0.x + v0.y) + (v0.z + v0.w))
                                    + ((v1.x + v1.y) + (v1.z + v1.w))
                                    + ((v2.x + v2.y) + (v2.z + v2.w))
                                    + ((v3.x + v3.y) + (v3.z + v3.w));
                    const float xv = xr[(size_t)(base + r) * DMODEL];
                    yr[(size_t)(base + r) * DMODEL] = fmaf(Dd, xv, sum);
                }
            }
            // no second barrier: buffer `buf` is re-written only after the
            // NEXT __syncthreads, by which time all reads have completed.
        }
    }
}

extern "C" void kernel_launch(void* const* d_in, const int* in_sizes, int n_in,
                              void* d_out, int out_size)
{
    const float* x      = (const float*)d_in[0];  // [8, 2048, 1024]
    const float* log_dt = (const float*)d_in[1];  // [1024]
    const float* Bm     = (const float*)d_in[2];  // [1024, 64]
    const float* Cm     = (const float*)d_in[3];  // [1024, 64]
    const float* Dv     = (const float*)d_in[4];  // [1024]
    float*       y      = (float*)d_out;          // [8, 2048, 1024]

    dim3 grid(DMODEL / CHT, BATCH);   // (64, 8) = 512 blocks
    dim3 block(WARPS * 32);           // 256 threads
    s4d_recurrence_kernel<<<grid, block>>>(x, log_dt, Bm, Cm, Dv, y);
}